// round 12
// baseline (speedup 1.0000x reference)
#include <cuda_runtime.h>
#include <cstdint>

#define HID 128
#define NN 50000
#define NE 800000
#define NG 64
#define NL 2

#define SCAN_B 512
#define SCAN_BLOCKS ((NN + SCAN_B - 1) / SCAN_B)   // 98

// ---------------- scratch (static device allocations) ----------------
__device__ __align__(16) float g_Xn[NN * HID];   // layer0 input (embedded)
__device__ __align__(16) float g_M[NN * HID];    // Xn + aggregation (gemm input)
__device__ __align__(16) float g_R[NN * HID];    // layer raw output
__device__ __align__(16) uint32_t g_Wf[4 * 32768]; // fragment-major hi/lo weights
__device__ int g_cnt[NN];
__device__ int g_off[NN + 1];
__device__ int g_cur[NN];
__device__ int g_bsum[SCAN_BLOCKS];
__device__ int g_boff[SCAN_BLOCKS];
__device__ int g_list[NE];
__device__ double g_sum[HID];
__device__ double g_sumsq[HID];
__device__ __align__(16) float g_scale[HID];
__device__ __align__(16) float g_shift[HID];

__device__ __forceinline__ uint32_t f2tf32(float v) {
    uint32_t o;
    asm("cvt.rna.tf32.f32 %0, %1;" : "=r"(o) : "f"(v));
    return o;
}
__device__ __forceinline__ void split_tf32(float v, uint32_t& h, uint32_t& l) {
    h = f2tf32(v);
    l = f2tf32(v - __uint_as_float(h));
}

#define MMA_TF32(d, a, b) \
    asm volatile("mma.sync.aligned.m16n8k8.row.col.f32.tf32.tf32.f32 " \
        "{%0,%1,%2,%3}, {%4,%5,%6,%7}, {%8,%9}, {%0,%1,%2,%3};" \
        : "+f"((d)[0]), "+f"((d)[1]), "+f"((d)[2]), "+f"((d)[3]) \
        : "r"((a)[0]), "r"((a)[1]), "r"((a)[2]), "r"((a)[3]), \
          "r"((b)[0]), "r"((b)[1]))

// ---------------- weight prep (also zeros g_cnt) ----------------
__global__ void prep_w_kernel(const float* __restrict__ W1, const float* __restrict__ W2) {
    int i = blockIdx.x * blockDim.x + threadIdx.x;
    if (i < NN) g_cnt[i] = 0;
    if (i >= 4 * HID * HID) return;
    int w = i >> 14;
    int k = (i >> 7) & 127;
    int n = i & 127;
    int l = w >> 1;
    const float* W = (w & 1) ? W2 : W1;
    float v = __ldg(W + l * HID * HID + k * HID + n);
    uint32_t h, lo;
    split_tf32(v, h, lo);
    int lane = (n & 7) * 4 + (k & 3);
    int word = (k >> 2) & 1;
    int base4 = ((w * 256 + (k >> 3) * 16 + (n >> 3)) * 32 + lane) * 4;
    g_Wf[base4 + word] = h;
    g_Wf[base4 + 2 + word] = lo;
}

// ---------------- CSR build (once per call; graph is layer-invariant) ----------------
__global__ void hist_kernel(const int* __restrict__ ei) {
    int e = blockIdx.x * blockDim.x + threadIdx.x;
    if (e < NE) atomicAdd(&g_cnt[__ldg(ei + NE + e)], 1);
}
__global__ void scan1_kernel() {
    __shared__ int sh[SCAN_B];
    int tid = threadIdx.x;
    int i = blockIdx.x * SCAN_B + tid;
    int v = (i < NN) ? g_cnt[i] : 0;
    sh[tid] = v;
    __syncthreads();
#pragma unroll
    for (int d = 1; d < SCAN_B; d <<= 1) {
        int t = (tid >= d) ? sh[tid - d] : 0;
        __syncthreads();
        sh[tid] += t;
        __syncthreads();
    }
    if (i < NN) g_off[i] = sh[tid] - v;
    if (tid == SCAN_B - 1) g_bsum[blockIdx.x] = sh[tid];
}
__global__ void scan2_kernel() {
    __shared__ int sh[128];
    int tid = threadIdx.x;
    int v = (tid < SCAN_BLOCKS) ? g_bsum[tid] : 0;
    sh[tid] = v;
    __syncthreads();
#pragma unroll
    for (int d = 1; d < 128; d <<= 1) {
        int t = (tid >= d) ? sh[tid - d] : 0;
        __syncthreads();
        sh[tid] += t;
        __syncthreads();
    }
    if (tid < SCAN_BLOCKS) g_boff[tid] = sh[tid] - v;
}
__global__ void scan3_kernel() {
    int i = blockIdx.x * SCAN_B + threadIdx.x;
    if (i < NN) {
        int o = g_off[i] + g_boff[blockIdx.x];
        g_off[i] = o;
        g_cur[i] = o;
    }
    if (i == 0) g_off[NN] = NE;
}
__global__ void scatter_kernel(const int* __restrict__ ei, const int* __restrict__ ea) {
    int e = blockIdx.x * blockDim.x + threadIdx.x;
    if (e >= NE) return;
    int src = __ldg(ei + e);
    int dst = __ldg(ei + NE + e);
    int attr = __ldg(ea + e);
    int p = atomicAdd(&g_cur[dst], 1);
    g_list[p] = (src << 2) | attr;
}

// ---------------- embed: Xn = node_emb[x_idx] ----------------
__global__ void embed_kernel(const int* __restrict__ xi, const float* __restrict__ nemb) {
    int i = blockIdx.x * blockDim.x + threadIdx.x;
    if (i >= NN * (HID / 4)) return;
    int n = i >> 5;
    int c = i & 31;
    ((float4*)g_Xn)[i] = __ldg((const float4*)(nemb + xi[n] * HID) + c);
}

// ---------------- aggregate: M[n] = x(n) + sum_{e->n} relu(x(src)+eemb[attr]) ----------------
// NORM: x(v) = norm(X[v]) applied inline (layer >= 1 reads raw R); else x(v) = X[v].
// 4-edge batches: packed entries loaded first, then 4 independent row-gathers (MLP=4).
template <bool NORM>
__global__ void aggregate_kernel(const float* __restrict__ X, float* __restrict__ M,
                                 const float* __restrict__ eemb) {
    int node = (blockIdx.x * blockDim.x + threadIdx.x) >> 5;
    int lane = threadIdx.x & 31;
    if (node >= NN) return;
    float4 sc, sh;
    if (NORM) {
        sc = *(const float4*)(g_scale + lane * 4);
        sh = *(const float4*)(g_shift + lane * 4);
    }
    // preload all 4 edge-embedding rows (attrs are 0..3)
    float4 em[4];
#pragma unroll
    for (int a = 0; a < 4; a++)
        em[a] = __ldg((const float4*)(eemb + a * HID) + lane);

    int s = g_off[node];
    int e = g_off[node + 1];
    float4 acc = __ldg((const float4*)(X + node * HID) + lane);
    if (NORM) {
        acc.x = fmaf(acc.x, sc.x, sh.x);
        acc.y = fmaf(acc.y, sc.y, sh.y);
        acc.z = fmaf(acc.z, sc.z, sh.z);
        acc.w = fmaf(acc.w, sc.w, sh.w);
    }

    int i = s;
    for (; i + 4 <= e; i += 4) {
        int pk0 = __ldg(g_list + i);
        int pk1 = __ldg(g_list + i + 1);
        int pk2 = __ldg(g_list + i + 2);
        int pk3 = __ldg(g_list + i + 3);
        float4 x0 = __ldg((const float4*)(X + (size_t)(pk0 >> 2) * HID) + lane);
        float4 x1 = __ldg((const float4*)(X + (size_t)(pk1 >> 2) * HID) + lane);
        float4 x2 = __ldg((const float4*)(X + (size_t)(pk2 >> 2) * HID) + lane);
        float4 x3 = __ldg((const float4*)(X + (size_t)(pk3 >> 2) * HID) + lane);
#define ACC_EDGE(xv, pk) do { \
        float4 _e = em[(pk) & 3]; \
        float _a, _b, _c, _d; \
        if (NORM) { \
            _a = fmaf((xv).x, sc.x, sh.x) + _e.x; \
            _b = fmaf((xv).y, sc.y, sh.y) + _e.y; \
            _c = fmaf((xv).z, sc.z, sh.z) + _e.z; \
            _d = fmaf((xv).w, sc.w, sh.w) + _e.w; \
        } else { \
            _a = (xv).x + _e.x; _b = (xv).y + _e.y; \
            _c = (xv).z + _e.z; _d = (xv).w + _e.w; \
        } \
        acc.x += fmaxf(_a, 0.f); acc.y += fmaxf(_b, 0.f); \
        acc.z += fmaxf(_c, 0.f); acc.w += fmaxf(_d, 0.f); \
    } while (0)
        ACC_EDGE(x0, pk0);
        ACC_EDGE(x1, pk1);
        ACC_EDGE(x2, pk2);
        ACC_EDGE(x3, pk3);
    }
    for (; i < e; i++) {
        int pk = __ldg(g_list + i);
        float4 xv = __ldg((const float4*)(X + (size_t)(pk >> 2) * HID) + lane);
        ACC_EDGE(xv, pk);
    }
#undef ACC_EDGE
    *((float4*)(M + node * HID) + lane) = acc;
}

// ---------------- fused 3xTF32 double-GEMM: R = relu(relu(M@W1+b1)@W2+b2) ----------------
#define MTILE 128
#define RS 36
#define RS2 132
#define RAW_WORDS (MTILE * RS)
#define STAT_OFF (2 * RAW_WORDS)
#define AS_OFF (STAT_OFF + 256)
#define SMEM_GEMM ((AS_OFF + MTILE * RS2) * 4)

__global__ void __launch_bounds__(256, 2)
fused_gemm_kernel(const float* __restrict__ M, const uint4* __restrict__ Wf1,
                  const float* __restrict__ b1, const uint4* __restrict__ Wf2,
                  const float* __restrict__ b2, float* __restrict__ R) {
    extern __shared__ char smem[];
    float* raw = (float*)smem;
    float* ssum = (float*)smem + STAT_OFF;
    float* ssq = ssum + 128;
    float* As = (float*)smem + AS_OFF;

    uint32_t rawAddr;
    asm("{ .reg .u64 t; cvta.to.shared.u64 t, %1; cvt.u32.u64 %0, t; }"
        : "=r"(rawAddr) : "l"(smem));

    int tid = threadIdx.x, wid = tid >> 5, lane = tid & 31;
    int wm = wid & 3, wn = wid >> 2;
    int g = lane >> 2, tg = lane & 3;
    int rowBase = blockIdx.x * MTILE;

    ssum[tid] = 0.f;

    auto issue_chunk = [&](int chunk, int buf) {
#pragma unroll
        for (int j = 0; j < 4; j++) {
            int i = tid + j * 256;
            int r = i >> 3, q = i & 7;
            int grow = rowBase + r;
            const float* src = M + (size_t)min(grow, NN - 1) * HID + chunk * 32 + q * 4;
            uint32_t dst = rawAddr + (uint32_t)(buf * RAW_WORDS + r * RS + q * 4) * 4u;
            int sz = (grow < NN) ? 16 : 0;
            asm volatile("cp.async.cg.shared.global [%0], [%1], 16, %2;"
                         :: "r"(dst), "l"(src), "r"(sz));
        }
        asm volatile("cp.async.commit_group;");
    };
    issue_chunk(0, 0);
    issue_chunk(1, 1);

    float acc[2][8][4];
#pragma unroll
    for (int mt = 0; mt < 2; mt++)
#pragma unroll
        for (int nt = 0; nt < 8; nt++)
#pragma unroll
            for (int c = 0; c < 4; c++) acc[mt][nt][c] = 0.f;

    // ---------------- phase 1 mainloop: acc1 = M @ W1 ----------------
    const uint4* wfw1 = Wf1 + (size_t)(wn * 8) * 32 + lane;
#pragma unroll
    for (int chunk = 0; chunk < 4; chunk++) {
        if (chunk < 3) asm volatile("cp.async.wait_group 1;" ::: "memory");
        else           asm volatile("cp.async.wait_group 0;" ::: "memory");
        __syncthreads();
        const float* rb = raw + (chunk & 1) * RAW_WORDS;

#pragma unroll
        for (int ks = 0; ks < 4; ks++) {
            int k0 = ks * 8;
            int kstep = chunk * 4 + ks;
            const uint4* wfk = wfw1 + (size_t)kstep * 16 * 32;

            uint32_t afH[2][4], afL[2][4];
#pragma unroll
            for (int mt = 0; mt < 2; mt++) {
                int r = wm * 32 + mt * 16 + g;
                float v0 = rb[r * RS + k0 + tg];
                float v1 = rb[(r + 8) * RS + k0 + tg];
                float v2 = rb[r * RS + k0 + tg + 4];
                float v3 = rb[(r + 8) * RS + k0 + tg + 4];
                split_tf32(v0, afH[mt][0], afL[mt][0]);
                split_tf32(v1, afH[mt][1], afL[mt][1]);
                split_tf32(v2, afH[mt][2], afL[mt][2]);
                split_tf32(v3, afH[mt][3], afL[mt][3]);
            }
#pragma unroll
            for (int hb = 0; hb < 2; hb++) {
                uint4 bf[4];
#pragma unroll
                for (int q = 0; q < 4; q++)
                    bf[q] = __ldg(wfk + (hb * 4 + q) * 32);
#pragma unroll
                for (int mt = 0; mt < 2; mt++)
#pragma unroll
                    for (int q = 0; q < 4; q++) {
                        int nt = hb * 4 + q;
                        uint32_t bh[2] = {bf[q].x, bf[q].y};
                        uint32_t bl[2] = {bf[q].z, bf[q].w};
                        MMA_TF32(acc[mt][nt], afH[mt], bl);
                        MMA_TF32(acc[mt][nt], afL[mt], bh);
                        MMA_TF32(acc[mt][nt], afH[mt], bh);
                    }
            }
        }
        __syncthreads();
        if (chunk < 2) issue_chunk(chunk + 2, chunk & 1);
    }

    // ---------------- phase 1 epilogue: As = relu(acc1 + b1) ----------------
#pragma unroll
    for (int nt = 0; nt < 8; nt++) {
        int col = wn * 64 + nt * 8 + tg * 2;
        float2 bv = __ldg((const float2*)(b1 + col));
#pragma unroll
        for (int mt = 0; mt < 2; mt++) {
            int r = wm * 32 + mt * 16 + g;
            float2 oa, ob;
            oa.x = fmaxf(acc[mt][nt][0] + bv.x, 0.f);
            oa.y = fmaxf(acc[mt][nt][1] + bv.y, 0.f);
            ob.x = fmaxf(acc[mt][nt][2] + bv.x, 0.f);
            ob.y = fmaxf(acc[mt][nt][3] + bv.y, 0.f);
            *(float2*)(As + r * RS2 + col) = oa;
            *(float2*)(As + (r + 8) * RS2 + col) = ob;
            acc[mt][nt][0] = 0.f; acc[mt][nt][1] = 0.f;
            acc[mt][nt][2] = 0.f; acc[mt][nt][3] = 0.f;
        }
    }
    __syncthreads();

    // ---------------- phase 2 mainloop: acc2 = As @ W2 ----------------
    const uint4* wfw2 = Wf2 + (size_t)(wn * 8) * 32 + lane;
#pragma unroll
    for (int kstep = 0; kstep < 16; kstep++) {
        int k0 = kstep * 8;
        const uint4* wfk = wfw2 + (size_t)kstep * 16 * 32;

        uint32_t afH[2][4], afL[2][4];
#pragma unroll
        for (int mt = 0; mt < 2; mt++) {
            int r = wm * 32 + mt * 16 + g;
            float v0 = As[r * RS2 + k0 + tg];
            float v1 = As[(r + 8) * RS2 + k0 + tg];
            float v2 = As[r * RS2 + k0 + tg + 4];
            float v3 = As[(r + 8) * RS2 + k0 + tg + 4];
            split_tf32(v0, afH[mt][0], afL[mt][0]);
            split_tf32(v1, afH[mt][1], afL[mt][1]);
            split_tf32(v2, afH[mt][2], afL[mt][2]);
            split_tf32(v3, afH[mt][3], afL[mt][3]);
        }
#pragma unroll
        for (int hb = 0; hb < 2; hb++) {
            uint4 bf[4];
#pragma unroll
            for (int q = 0; q < 4; q++)
                bf[q] = __ldg(wfk + (hb * 4 + q) * 32);
#pragma unroll
            for (int mt = 0; mt < 2; mt++)
#pragma unroll
                for (int q = 0; q < 4; q++) {
                    int nt = hb * 4 + q;
                    uint32_t bh[2] = {bf[q].x, bf[q].y};
                    uint32_t bl[2] = {bf[q].z, bf[q].w};
                    MMA_TF32(acc[mt][nt], afH[mt], bl);
                    MMA_TF32(acc[mt][nt], afL[mt], bh);
                    MMA_TF32(acc[mt][nt], afH[mt], bh);
                }
        }
    }

    // ---------------- phase 2 epilogue: R = relu(acc2 + b2), column stats ----------------
#pragma unroll
    for (int nt = 0; nt < 8; nt++) {
        int col = wn * 64 + nt * 8 + tg * 2;
        float2 bv = __ldg((const float2*)(b2 + col));
        float s0 = 0.f, s1 = 0.f, q0 = 0.f, q1 = 0.f;
#pragma unroll
        for (int mt = 0; mt < 2; mt++) {
            int r0 = rowBase + wm * 32 + mt * 16 + g;
            float2 oa, ob;
            oa.x = fmaxf(acc[mt][nt][0] + bv.x, 0.f);
            oa.y = fmaxf(acc[mt][nt][1] + bv.y, 0.f);
            ob.x = fmaxf(acc[mt][nt][2] + bv.x, 0.f);
            ob.y = fmaxf(acc[mt][nt][3] + bv.y, 0.f);
            if (r0 < NN) {
                *(float2*)(R + r0 * HID + col) = oa;
                s0 += oa.x; q0 += oa.x * oa.x; s1 += oa.y; q1 += oa.y * oa.y;
            }
            if (r0 + 8 < NN) {
                *(float2*)(R + (r0 + 8) * HID + col) = ob;
                s0 += ob.x; q0 += ob.x * ob.x; s1 += ob.y; q1 += ob.y * ob.y;
            }
        }
#pragma unroll
        for (int m = 16; m >= 4; m >>= 1) {
            s0 += __shfl_xor_sync(0xffffffff, s0, m);
            s1 += __shfl_xor_sync(0xffffffff, s1, m);
            q0 += __shfl_xor_sync(0xffffffff, q0, m);
            q1 += __shfl_xor_sync(0xffffffff, q1, m);
        }
        if (lane < 4) {
            int c0 = wn * 64 + nt * 8 + lane * 2;
            atomicAdd(&ssum[c0], s0);
            atomicAdd(&ssum[c0 + 1], s1);
            atomicAdd(&ssq[c0], q0);
            atomicAdd(&ssq[c0 + 1], q1);
        }
    }
    __syncthreads();
    if (tid < 128) {
        atomicAdd(&g_sum[tid], (double)ssum[tid]);
        atomicAdd(&g_sumsq[tid], (double)ssq[tid]);
    }
}

// ---------------- finalize: scale/shift from stats; reset accumulators ----------------
__global__ void finalize_kernel(const float* __restrict__ gw, const float* __restrict__ bw) {
    int c = threadIdx.x;
    double mu = g_sum[c] / (double)NN;
    double var = g_sumsq[c] / (double)NN - mu * mu;
    float sc = (float)((double)gw[c] * rsqrt(var + 1e-5));
    g_scale[c] = sc;
    g_shift[c] = bw[c] - (float)mu * sc;
    g_sum[c] = 0.0;
    g_sumsq[c] = 0.0;
}

// ---------------- pooling (applies final norm inline) ----------------
__global__ void zero_out_kernel(float* out) {
    int i = blockIdx.x * blockDim.x + threadIdx.x;
    if (i < NG * HID) out[i] = 0.f;
}

__global__ void pool_kernel(const float* __restrict__ R, const int* __restrict__ batch,
                            float* __restrict__ out) {
    int warp = (blockIdx.x * blockDim.x + threadIdx.x) >> 5;
    int lane = threadIdx.x & 31;
    if (warp >= NN) return;
    float4 sc = *(const float4*)(g_scale + lane * 4);
    float4 sh = *(const float4*)(g_shift + lane * 4);
    int g = __ldg(batch + warp);
    float4 v = __ldg((const float4*)(R + warp * HID) + lane);
    v.x = fmaf(v.x, sc.x, sh.x);
    v.y = fmaf(v.y, sc.y, sh.y);
    v.z = fmaf(v.z, sc.z, sh.z);
    v.w = fmaf(v.w, sc.w, sh.w);
    float* p = out + g * HID + lane * 4;
    asm volatile("red.global.add.v4.f32 [%0], {%1,%2,%3,%4};"
                 :: "l"(p), "f"(v.x), "f"(v.y), "f"(v.z), "f"(v.w) : "memory");
}

// ---------------- host ----------------
extern "C" void kernel_launch(void* const* d_in, const int* in_sizes, int n_in,
                              void* d_out, int out_size) {
    const int*   x_idx      = (const int*)d_in[0];
    const int*   edge_index = (const int*)d_in[1];
    const int*   edge_attr  = (const int*)d_in[2];
    const int*   batch      = (const int*)d_in[3];
    const float* node_emb   = (const float*)d_in[4];
    const float* edge_emb   = (const float*)d_in[5];
    const float* W1         = (const float*)d_in[6];
    const float* b1         = (const float*)d_in[7];
    const float* W2         = (const float*)d_in[8];
    const float* b2         = (const float*)d_in[9];
    const float* bn_g       = (const float*)d_in[10];
    const float* bn_b       = (const float*)d_in[11];
    float* out = (float*)d_out;

    cudaFuncSetAttribute(fused_gemm_kernel,
                         cudaFuncAttributeMaxDynamicSharedMemorySize, SMEM_GEMM);

    float *Xn, *M, *R;
    uint4* Wf;
    cudaGetSymbolAddress((void**)&Xn, g_Xn);
    cudaGetSymbolAddress((void**)&M, g_M);
    cudaGetSymbolAddress((void**)&R, g_R);
    cudaGetSymbolAddress((void**)&Wf, g_Wf);

    int nf4 = NN * (HID / 4);
    int cpBlocks = (nf4 + 255) / 256;
    int gemmBlocks = (NN + MTILE - 1) / MTILE;

    prep_w_kernel<<<(4 * HID * HID + 255) / 256, 256>>>(W1, W2);
    hist_kernel<<<(NE + 255) / 256, 256>>>(edge_index);
    scan1_kernel<<<SCAN_BLOCKS, SCAN_B>>>();
    scan2_kernel<<<1, 128>>>();
    scan3_kernel<<<SCAN_BLOCKS, SCAN_B>>>();
    scatter_kernel<<<(NE + 255) / 256, 256>>>(edge_index, edge_attr);
    embed_kernel<<<cpBlocks, 256>>>(x_idx, node_emb);

    for (int l = 0; l < NL; l++) {
        if (l == 0)
            aggregate_kernel<false><<<(NN * 32 + 255) / 256, 256>>>(Xn, M, edge_emb);
        else
            aggregate_kernel<true><<<(NN * 32 + 255) / 256, 256>>>(R, M, edge_emb);
        fused_gemm_kernel<<<gemmBlocks, 256, SMEM_GEMM>>>(
            M, Wf + (size_t)(l * 2 + 0) * 8192, b1 + l * HID,
            Wf + (size_t)(l * 2 + 1) * 8192, b2 + l * HID, R);
        finalize_kernel<<<1, 128>>>(bn_g + l * HID, bn_b + l * HID);
    }

    zero_out_kernel<<<(NG * HID + 255) / 256, 256>>>(out);
    pool_kernel<<<NN * 32 / 256, 256>>>(R, batch, out);
}

// round 13
// speedup vs baseline: 1.0887x; 1.0887x over previous
#include <cuda_runtime.h>
#include <cstdint>

#define HID 128
#define NN 50000
#define NE 800000
#define NG 64
#define NL 2

#define SCAN_B 512
#define SCAN_BLOCKS ((NN + SCAN_B - 1) / SCAN_B)   // 98

// ---------------- scratch (static device allocations) ----------------
__device__ __align__(16) float g_Xn[NN * HID];   // layer0 input (embedded)
__device__ __align__(16) float g_M[NN * HID];    // x + aggregation (gemm input)
__device__ __align__(16) float g_R[NN * HID];    // layer raw output
__device__ __align__(16) uint32_t g_Wf[4 * 32768]; // fragment-major hi/lo weights
__device__ int g_cnt[NN];
__device__ int g_off[NN + 1];
__device__ int g_cur[NN];
__device__ int g_bsum[SCAN_BLOCKS];
__device__ int g_boff[SCAN_BLOCKS];
__device__ int g_list[NE];
__device__ double g_sum[HID];
__device__ double g_sumsq[HID];
__device__ __align__(16) float g_scale[HID];
__device__ __align__(16) float g_shift[HID];

__device__ __forceinline__ uint32_t f2tf32(float v) {
    uint32_t o;
    asm("cvt.rna.tf32.f32 %0, %1;" : "=r"(o) : "f"(v));
    return o;
}
__device__ __forceinline__ void split_tf32(float v, uint32_t& h, uint32_t& l) {
    h = f2tf32(v);
    l = f2tf32(v - __uint_as_float(h));
}

#define MMA_TF32(d, a, b) \
    asm volatile("mma.sync.aligned.m16n8k8.row.col.f32.tf32.tf32.f32 " \
        "{%0,%1,%2,%3}, {%4,%5,%6,%7}, {%8,%9}, {%0,%1,%2,%3};" \
        : "+f"((d)[0]), "+f"((d)[1]), "+f"((d)[2]), "+f"((d)[3]) \
        : "r"((a)[0]), "r"((a)[1]), "r"((a)[2]), "r"((a)[3]), \
          "r"((b)[0]), "r"((b)[1]))

// ---------------- weight prep (also zeros g_cnt) ----------------
__global__ void prep_w_kernel(const float* __restrict__ W1, const float* __restrict__ W2) {
    int i = blockIdx.x * blockDim.x + threadIdx.x;
    if (i < NN) g_cnt[i] = 0;
    if (i >= 4 * HID * HID) return;
    int w = i >> 14;
    int k = (i >> 7) & 127;
    int n = i & 127;
    int l = w >> 1;
    const float* W = (w & 1) ? W2 : W1;
    float v = __ldg(W + l * HID * HID + k * HID + n);
    uint32_t h, lo;
    split_tf32(v, h, lo);
    int lane = (n & 7) * 4 + (k & 3);
    int word = (k >> 2) & 1;
    int base4 = ((w * 256 + (k >> 3) * 16 + (n >> 3)) * 32 + lane) * 4;
    g_Wf[base4 + word] = h;
    g_Wf[base4 + 2 + word] = lo;
}

// ---------------- CSR build (once per call; graph is layer-invariant) ----------------
__global__ void hist_kernel(const int* __restrict__ ei) {
    int e = blockIdx.x * blockDim.x + threadIdx.x;
    if (e < NE) atomicAdd(&g_cnt[__ldg(ei + NE + e)], 1);
}
__global__ void scan1_kernel() {
    __shared__ int sh[SCAN_B];
    int tid = threadIdx.x;
    int i = blockIdx.x * SCAN_B + tid;
    int v = (i < NN) ? g_cnt[i] : 0;
    sh[tid] = v;
    __syncthreads();
#pragma unroll
    for (int d = 1; d < SCAN_B; d <<= 1) {
        int t = (tid >= d) ? sh[tid - d] : 0;
        __syncthreads();
        sh[tid] += t;
        __syncthreads();
    }
    if (i < NN) g_off[i] = sh[tid] - v;
    if (tid == SCAN_B - 1) g_bsum[blockIdx.x] = sh[tid];
}
__global__ void scan2_kernel() {
    __shared__ int sh[128];
    int tid = threadIdx.x;
    int v = (tid < SCAN_BLOCKS) ? g_bsum[tid] : 0;
    sh[tid] = v;
    __syncthreads();
#pragma unroll
    for (int d = 1; d < 128; d <<= 1) {
        int t = (tid >= d) ? sh[tid - d] : 0;
        __syncthreads();
        sh[tid] += t;
        __syncthreads();
    }
    if (tid < SCAN_BLOCKS) g_boff[tid] = sh[tid] - v;
}
__global__ void scan3_kernel() {
    int i = blockIdx.x * SCAN_B + threadIdx.x;
    if (i < NN) {
        int o = g_off[i] + g_boff[blockIdx.x];
        g_off[i] = o;
        g_cur[i] = o;
    }
    if (i == 0) g_off[NN] = NE;
}
__global__ void scatter_kernel(const int* __restrict__ ei, const int* __restrict__ ea) {
    int e = blockIdx.x * blockDim.x + threadIdx.x;
    if (e >= NE) return;
    int src = __ldg(ei + e);
    int dst = __ldg(ei + NE + e);
    int attr = __ldg(ea + e);
    int p = atomicAdd(&g_cur[dst], 1);
    g_list[p] = (src << 2) | attr;
}

// ---------------- embed: Xn = node_emb[x_idx] ----------------
__global__ void embed_kernel(const int* __restrict__ xi, const float* __restrict__ nemb) {
    int i = blockIdx.x * blockDim.x + threadIdx.x;
    if (i >= NN * (HID / 4)) return;
    int n = i >> 5;
    int c = i & 31;
    ((float4*)g_Xn)[i] = __ldg((const float4*)(nemb + xi[n] * HID) + c);
}

// ---------------- aggregate: M[n] = x(n) + sum_{e->n} relu(x(src)+eemb[attr]) ----------------
// NORM: x(v) = norm(X[v]) applied inline (layer >= 1 reads raw R); else x(v) = X[v].
// Serial edge loop (R11 structure — batched MLP caused L1tex-queue spread, R12 post-mortem).
template <bool NORM>
__global__ void aggregate_kernel(const float* __restrict__ X, float* __restrict__ M,
                                 const float* __restrict__ eemb) {
    int node = (blockIdx.x * blockDim.x + threadIdx.x) >> 5;
    int lane = threadIdx.x & 31;
    if (node >= NN) return;
    float4 sc, sh;
    if (NORM) {
        sc = *(const float4*)(g_scale + lane * 4);
        sh = *(const float4*)(g_shift + lane * 4);
    }
    int s = g_off[node];
    int e = g_off[node + 1];
    float4 acc = __ldg((const float4*)(X + node * HID) + lane);
    if (NORM) {
        acc.x = fmaf(acc.x, sc.x, sh.x);
        acc.y = fmaf(acc.y, sc.y, sh.y);
        acc.z = fmaf(acc.z, sc.z, sh.z);
        acc.w = fmaf(acc.w, sc.w, sh.w);
    }
    for (int i = s; i < e; i++) {
        int pk = __ldg(g_list + i);
        int src = pk >> 2, attr = pk & 3;
        float4 x4 = __ldg((const float4*)(X + (size_t)src * HID) + lane);
        float4 e4 = __ldg((const float4*)(eemb + attr * HID) + lane);
        float a, b, c, d;
        if (NORM) {
            a = fmaf(x4.x, sc.x, sh.x) + e4.x;
            b = fmaf(x4.y, sc.y, sh.y) + e4.y;
            c = fmaf(x4.z, sc.z, sh.z) + e4.z;
            d = fmaf(x4.w, sc.w, sh.w) + e4.w;
        } else {
            a = x4.x + e4.x; b = x4.y + e4.y;
            c = x4.z + e4.z; d = x4.w + e4.w;
        }
        acc.x += fmaxf(a, 0.f);
        acc.y += fmaxf(b, 0.f);
        acc.z += fmaxf(c, 0.f);
        acc.w += fmaxf(d, 0.f);
    }
    *((float4*)(M + node * HID) + lane) = acc;
}

// ---------------- fused 3xTF32 double-GEMM: R = relu(relu(M@W1+b1)@W2+b2) ----------------
#define MTILE 128
#define RS 36
#define RS2 132
#define RAW_WORDS (MTILE * RS)
#define STAT_OFF (2 * RAW_WORDS)
#define AS_OFF (STAT_OFF + 256)
#define SMEM_GEMM ((AS_OFF + MTILE * RS2) * 4)

__global__ void __launch_bounds__(256, 2)
fused_gemm_kernel(const float* __restrict__ M, const uint4* __restrict__ Wf1,
                  const float* __restrict__ b1, const uint4* __restrict__ Wf2,
                  const float* __restrict__ b2, float* __restrict__ R) {
    extern __shared__ char smem[];
    float* raw = (float*)smem;
    float* ssum = (float*)smem + STAT_OFF;
    float* ssq = ssum + 128;
    float* As = (float*)smem + AS_OFF;

    uint32_t rawAddr;
    asm("{ .reg .u64 t; cvta.to.shared.u64 t, %1; cvt.u32.u64 %0, t; }"
        : "=r"(rawAddr) : "l"(smem));

    int tid = threadIdx.x, wid = tid >> 5, lane = tid & 31;
    int wm = wid & 3, wn = wid >> 2;
    int g = lane >> 2, tg = lane & 3;
    int rowBase = blockIdx.x * MTILE;

    ssum[tid] = 0.f;

    auto issue_chunk = [&](int chunk, int buf) {
#pragma unroll
        for (int j = 0; j < 4; j++) {
            int i = tid + j * 256;
            int r = i >> 3, q = i & 7;
            int grow = rowBase + r;
            const float* src = M + (size_t)min(grow, NN - 1) * HID + chunk * 32 + q * 4;
            uint32_t dst = rawAddr + (uint32_t)(buf * RAW_WORDS + r * RS + q * 4) * 4u;
            int sz = (grow < NN) ? 16 : 0;
            asm volatile("cp.async.cg.shared.global [%0], [%1], 16, %2;"
                         :: "r"(dst), "l"(src), "r"(sz));
        }
        asm volatile("cp.async.commit_group;");
    };
    issue_chunk(0, 0);
    issue_chunk(1, 1);

    float acc[2][8][4];
#pragma unroll
    for (int mt = 0; mt < 2; mt++)
#pragma unroll
        for (int nt = 0; nt < 8; nt++)
#pragma unroll
            for (int c = 0; c < 4; c++) acc[mt][nt][c] = 0.f;

    // ---------------- phase 1 mainloop: acc1 = M @ W1 ----------------
    const uint4* wfw1 = Wf1 + (size_t)(wn * 8) * 32 + lane;
#pragma unroll
    for (int chunk = 0; chunk < 4; chunk++) {
        if (chunk < 3) asm volatile("cp.async.wait_group 1;" ::: "memory");
        else           asm volatile("cp.async.wait_group 0;" ::: "memory");
        __syncthreads();
        const float* rb = raw + (chunk & 1) * RAW_WORDS;

#pragma unroll
        for (int ks = 0; ks < 4; ks++) {
            int k0 = ks * 8;
            int kstep = chunk * 4 + ks;
            const uint4* wfk = wfw1 + (size_t)kstep * 16 * 32;

            uint32_t afH[2][4], afL[2][4];
#pragma unroll
            for (int mt = 0; mt < 2; mt++) {
                int r = wm * 32 + mt * 16 + g;
                float v0 = rb[r * RS + k0 + tg];
                float v1 = rb[(r + 8) * RS + k0 + tg];
                float v2 = rb[r * RS + k0 + tg + 4];
                float v3 = rb[(r + 8) * RS + k0 + tg + 4];
                split_tf32(v0, afH[mt][0], afL[mt][0]);
                split_tf32(v1, afH[mt][1], afL[mt][1]);
                split_tf32(v2, afH[mt][2], afL[mt][2]);
                split_tf32(v3, afH[mt][3], afL[mt][3]);
            }
#pragma unroll
            for (int hb = 0; hb < 2; hb++) {
                uint4 bf[4];
#pragma unroll
                for (int q = 0; q < 4; q++)
                    bf[q] = __ldg(wfk + (hb * 4 + q) * 32);
#pragma unroll
                for (int mt = 0; mt < 2; mt++)
#pragma unroll
                    for (int q = 0; q < 4; q++) {
                        int nt = hb * 4 + q;
                        uint32_t bh[2] = {bf[q].x, bf[q].y};
                        uint32_t bl[2] = {bf[q].z, bf[q].w};
                        MMA_TF32(acc[mt][nt], afH[mt], bl);
                        MMA_TF32(acc[mt][nt], afL[mt], bh);
                        MMA_TF32(acc[mt][nt], afH[mt], bh);
                    }
            }
        }
        __syncthreads();
        if (chunk < 2) issue_chunk(chunk + 2, chunk & 1);
    }

    // ---------------- phase 1 epilogue: As = relu(acc1 + b1) ----------------
#pragma unroll
    for (int nt = 0; nt < 8; nt++) {
        int col = wn * 64 + nt * 8 + tg * 2;
        float2 bv = __ldg((const float2*)(b1 + col));
#pragma unroll
        for (int mt = 0; mt < 2; mt++) {
            int r = wm * 32 + mt * 16 + g;
            float2 oa, ob;
            oa.x = fmaxf(acc[mt][nt][0] + bv.x, 0.f);
            oa.y = fmaxf(acc[mt][nt][1] + bv.y, 0.f);
            ob.x = fmaxf(acc[mt][nt][2] + bv.x, 0.f);
            ob.y = fmaxf(acc[mt][nt][3] + bv.y, 0.f);
            *(float2*)(As + r * RS2 + col) = oa;
            *(float2*)(As + (r + 8) * RS2 + col) = ob;
            acc[mt][nt][0] = 0.f; acc[mt][nt][1] = 0.f;
            acc[mt][nt][2] = 0.f; acc[mt][nt][3] = 0.f;
        }
    }
    __syncthreads();

    // ---------------- phase 2 mainloop: acc2 = As @ W2 ----------------
    const uint4* wfw2 = Wf2 + (size_t)(wn * 8) * 32 + lane;
#pragma unroll
    for (int kstep = 0; kstep < 16; kstep++) {
        int k0 = kstep * 8;
        const uint4* wfk = wfw2 + (size_t)kstep * 16 * 32;

        uint32_t afH[2][4], afL[2][4];
#pragma unroll
        for (int mt = 0; mt < 2; mt++) {
            int r = wm * 32 + mt * 16 + g;
            float v0 = As[r * RS2 + k0 + tg];
            float v1 = As[(r + 8) * RS2 + k0 + tg];
            float v2 = As[r * RS2 + k0 + tg + 4];
            float v3 = As[(r + 8) * RS2 + k0 + tg + 4];
            split_tf32(v0, afH[mt][0], afL[mt][0]);
            split_tf32(v1, afH[mt][1], afL[mt][1]);
            split_tf32(v2, afH[mt][2], afL[mt][2]);
            split_tf32(v3, afH[mt][3], afL[mt][3]);
        }
#pragma unroll
        for (int hb = 0; hb < 2; hb++) {
            uint4 bf[4];
#pragma unroll
            for (int q = 0; q < 4; q++)
                bf[q] = __ldg(wfk + (hb * 4 + q) * 32);
#pragma unroll
            for (int mt = 0; mt < 2; mt++)
#pragma unroll
                for (int q = 0; q < 4; q++) {
                    int nt = hb * 4 + q;
                    uint32_t bh[2] = {bf[q].x, bf[q].y};
                    uint32_t bl[2] = {bf[q].z, bf[q].w};
                    MMA_TF32(acc[mt][nt], afH[mt], bl);
                    MMA_TF32(acc[mt][nt], afL[mt], bh);
                    MMA_TF32(acc[mt][nt], afH[mt], bh);
                }
        }
    }

    // ---------------- phase 2 epilogue: R = relu(acc2 + b2), column stats ----------------
#pragma unroll
    for (int nt = 0; nt < 8; nt++) {
        int col = wn * 64 + nt * 8 + tg * 2;
        float2 bv = __ldg((const float2*)(b2 + col));
        float s0 = 0.f, s1 = 0.f, q0 = 0.f, q1 = 0.f;
#pragma unroll
        for (int mt = 0; mt < 2; mt++) {
            int r0 = rowBase + wm * 32 + mt * 16 + g;
            float2 oa, ob;
            oa.x = fmaxf(acc[mt][nt][0] + bv.x, 0.f);
            oa.y = fmaxf(acc[mt][nt][1] + bv.y, 0.f);
            ob.x = fmaxf(acc[mt][nt][2] + bv.x, 0.f);
            ob.y = fmaxf(acc[mt][nt][3] + bv.y, 0.f);
            if (r0 < NN) {
                *(float2*)(R + r0 * HID + col) = oa;
                s0 += oa.x; q0 += oa.x * oa.x; s1 += oa.y; q1 += oa.y * oa.y;
            }
            if (r0 + 8 < NN) {
                *(float2*)(R + (r0 + 8) * HID + col) = ob;
                s0 += ob.x; q0 += ob.x * ob.x; s1 += ob.y; q1 += ob.y * ob.y;
            }
        }
#pragma unroll
        for (int m = 16; m >= 4; m >>= 1) {
            s0 += __shfl_xor_sync(0xffffffff, s0, m);
            s1 += __shfl_xor_sync(0xffffffff, s1, m);
            q0 += __shfl_xor_sync(0xffffffff, q0, m);
            q1 += __shfl_xor_sync(0xffffffff, q1, m);
        }
        if (lane < 4) {
            int c0 = wn * 64 + nt * 8 + lane * 2;
            atomicAdd(&ssum[c0], s0);
            atomicAdd(&ssum[c0 + 1], s1);
            atomicAdd(&ssq[c0], q0);
            atomicAdd(&ssq[c0 + 1], q1);
        }
    }
    __syncthreads();
    if (tid < 128) {
        atomicAdd(&g_sum[tid], (double)ssum[tid]);
        atomicAdd(&g_sumsq[tid], (double)ssq[tid]);
    }
}

// ---------------- finalize: scale/shift from stats; reset accumulators; optional out-zero ----------------
__global__ void finalize_kernel(const float* __restrict__ gw, const float* __restrict__ bw,
                                float* __restrict__ outz) {
    int c = threadIdx.x;
    double mu = g_sum[c] / (double)NN;
    double var = g_sumsq[c] / (double)NN - mu * mu;
    float sc = (float)((double)gw[c] * rsqrt(var + 1e-5));
    g_scale[c] = sc;
    g_shift[c] = bw[c] - (float)mu * sc;
    g_sum[c] = 0.0;
    g_sumsq[c] = 0.0;
    if (outz) {
        float4 z = make_float4(0.f, 0.f, 0.f, 0.f);
#pragma unroll
        for (int j = 0; j < NG * HID / 4 / 128; j++)
            ((float4*)outz)[c + j * 128] = z;
    }
}

// ---------------- pooling (applies final norm inline) ----------------
__global__ void pool_kernel(const float* __restrict__ R, const int* __restrict__ batch,
                            float* __restrict__ out) {
    int warp = (blockIdx.x * blockDim.x + threadIdx.x) >> 5;
    int lane = threadIdx.x & 31;
    if (warp >= NN) return;
    float4 sc = *(const float4*)(g_scale + lane * 4);
    float4 sh = *(const float4*)(g_shift + lane * 4);
    int g = __ldg(batch + warp);
    float4 v = __ldg((const float4*)(R + warp * HID) + lane);
    v.x = fmaf(v.x, sc.x, sh.x);
    v.y = fmaf(v.y, sc.y, sh.y);
    v.z = fmaf(v.z, sc.z, sh.z);
    v.w = fmaf(v.w, sc.w, sh.w);
    float* p = out + g * HID + lane * 4;
    asm volatile("red.global.add.v4.f32 [%0], {%1,%2,%3,%4};"
                 :: "l"(p), "f"(v.x), "f"(v.y), "f"(v.z), "f"(v.w) : "memory");
}

// ---------------- host ----------------
extern "C" void kernel_launch(void* const* d_in, const int* in_sizes, int n_in,
                              void* d_out, int out_size) {
    const int*   x_idx      = (const int*)d_in[0];
    const int*   edge_index = (const int*)d_in[1];
    const int*   edge_attr  = (const int*)d_in[2];
    const int*   batch      = (const int*)d_in[3];
    const float* node_emb   = (const float*)d_in[4];
    const float* edge_emb   = (const float*)d_in[5];
    const float* W1         = (const float*)d_in[6];
    const float* b1         = (const float*)d_in[7];
    const float* W2         = (const float*)d_in[8];
    const float* b2         = (const float*)d_in[9];
    const float* bn_g       = (const float*)d_in[10];
    const float* bn_b       = (const float*)d_in[11];
    float* out = (float*)d_out;

    cudaFuncSetAttribute(fused_gemm_kernel,
                         cudaFuncAttributeMaxDynamicSharedMemorySize, SMEM_GEMM);

    float *Xn, *M, *R;
    uint4* Wf;
    cudaGetSymbolAddress((void**)&Xn, g_Xn);
    cudaGetSymbolAddress((void**)&M, g_M);
    cudaGetSymbolAddress((void**)&R, g_R);
    cudaGetSymbolAddress((void**)&Wf, g_Wf);

    int nf4 = NN * (HID / 4);
    int cpBlocks = (nf4 + 255) / 256;
    int gemmBlocks = (NN + MTILE - 1) / MTILE;

    prep_w_kernel<<<(4 * HID * HID + 255) / 256, 256>>>(W1, W2);
    hist_kernel<<<(NE + 255) / 256, 256>>>(edge_index);
    scan1_kernel<<<SCAN_BLOCKS, SCAN_B>>>();
    scan2_kernel<<<1, 128>>>();
    scan3_kernel<<<SCAN_BLOCKS, SCAN_B>>>();
    scatter_kernel<<<(NE + 255) / 256, 256>>>(edge_index, edge_attr);
    embed_kernel<<<cpBlocks, 256>>>(x_idx, node_emb);

    for (int l = 0; l < NL; l++) {
        if (l == 0)
            aggregate_kernel<false><<<(NN * 32 + 255) / 256, 256>>>(Xn, M, edge_emb);
        else
            aggregate_kernel<true><<<(NN * 32 + 255) / 256, 256>>>(R, M, edge_emb);
        fused_gemm_kernel<<<gemmBlocks, 256, SMEM_GEMM>>>(
            M, Wf + (size_t)(l * 2 + 0) * 8192, b1 + l * HID,
            Wf + (size_t)(l * 2 + 1) * 8192, b2 + l * HID, R);
        finalize_kernel<<<1, 128>>>(bn_g + l * HID, bn_b + l * HID,
                                    (l == NL - 1) ? out : nullptr);
    }

    pool_kernel<<<NN * 32 / 256, 256>>>(R, batch, out);
}

// round 14
// speedup vs baseline: 1.1409x; 1.0479x over previous
#include <cuda_runtime.h>
#include <cstdint>

#define HID 128
#define NN 50000
#define NE 800000
#define NG 64
#define NL 2

#define SCAN_B 512
#define SCAN_BLOCKS ((NN + SCAN_B - 1) / SCAN_B)   // 98

// ---------------- scratch (static device allocations) ----------------
__device__ __align__(16) float g_M[NN * HID];    // x + aggregation (gemm input)
__device__ __align__(16) float g_R[NN * HID];    // layer raw output
__device__ __align__(16) uint32_t g_Wf[4 * 32768]; // fragment-major hi/lo weights
__device__ __align__(16) float g_T[76 * HID];    // layer-0 message table relu(nemb[i]+eemb[a])
__device__ int g_cnt[NN];
__device__ int g_off[NN + 1];
__device__ int g_cur[NN];
__device__ int g_bsum[SCAN_BLOCKS];
__device__ int g_boff[SCAN_BLOCKS];
__device__ int g_list[NE];
__device__ double g_sum[HID];
__device__ double g_sumsq[HID];
__device__ __align__(16) float g_scale[HID];
__device__ __align__(16) float g_shift[HID];

__device__ __forceinline__ uint32_t f2tf32(float v) {
    uint32_t o;
    asm("cvt.rna.tf32.f32 %0, %1;" : "=r"(o) : "f"(v));
    return o;
}
__device__ __forceinline__ void split_tf32(float v, uint32_t& h, uint32_t& l) {
    h = f2tf32(v);
    l = f2tf32(v - __uint_as_float(h));
}

#define MMA_TF32(d, a, b) \
    asm volatile("mma.sync.aligned.m16n8k8.row.col.f32.tf32.tf32.f32 " \
        "{%0,%1,%2,%3}, {%4,%5,%6,%7}, {%8,%9}, {%0,%1,%2,%3};" \
        : "+f"((d)[0]), "+f"((d)[1]), "+f"((d)[2]), "+f"((d)[3]) \
        : "r"((a)[0]), "r"((a)[1]), "r"((a)[2]), "r"((a)[3]), \
          "r"((b)[0]), "r"((b)[1]))

// ---------------- prep: weights (frag-major hi/lo), zero g_cnt, layer-0 msg table ----------------
__global__ void prep_w_kernel(const float* __restrict__ W1, const float* __restrict__ W2,
                              const float* __restrict__ nemb, const float* __restrict__ eemb) {
    int i = blockIdx.x * blockDim.x + threadIdx.x;
    if (i < NN) g_cnt[i] = 0;
    if (i < 76 * 32) {
        int t = i >> 5, lane = i & 31;
        int xe = t >> 2, at = t & 3;
        float4 n4 = __ldg((const float4*)(nemb + xe * HID) + lane);
        float4 e4 = __ldg((const float4*)(eemb + at * HID) + lane);
        float4 m;
        m.x = fmaxf(n4.x + e4.x, 0.f);
        m.y = fmaxf(n4.y + e4.y, 0.f);
        m.z = fmaxf(n4.z + e4.z, 0.f);
        m.w = fmaxf(n4.w + e4.w, 0.f);
        *((float4*)(g_T + t * HID) + lane) = m;
    }
    if (i >= 4 * HID * HID) return;
    int w = i >> 14;
    int k = (i >> 7) & 127;
    int n = i & 127;
    int l = w >> 1;
    const float* W = (w & 1) ? W2 : W1;
    float v = __ldg(W + l * HID * HID + k * HID + n);
    uint32_t h, lo;
    split_tf32(v, h, lo);
    int lane = (n & 7) * 4 + (k & 3);
    int word = (k >> 2) & 1;
    int base4 = ((w * 256 + (k >> 3) * 16 + (n >> 3)) * 32 + lane) * 4;
    g_Wf[base4 + word] = h;
    g_Wf[base4 + 2 + word] = lo;
}

// ---------------- CSR build (once per call; graph is layer-invariant) ----------------
__global__ void hist_kernel(const int* __restrict__ ei) {
    int e = blockIdx.x * blockDim.x + threadIdx.x;
    if (e < NE) atomicAdd(&g_cnt[__ldg(ei + NE + e)], 1);
}
__global__ void scan1_kernel() {
    __shared__ int sh[SCAN_B];
    int tid = threadIdx.x;
    int i = blockIdx.x * SCAN_B + tid;
    int v = (i < NN) ? g_cnt[i] : 0;
    sh[tid] = v;
    __syncthreads();
#pragma unroll
    for (int d = 1; d < SCAN_B; d <<= 1) {
        int t = (tid >= d) ? sh[tid - d] : 0;
        __syncthreads();
        sh[tid] += t;
        __syncthreads();
    }
    if (i < NN) g_off[i] = sh[tid] - v;
    if (tid == SCAN_B - 1) g_bsum[blockIdx.x] = sh[tid];
}
__global__ void scan2_kernel() {
    __shared__ int sh[128];
    int tid = threadIdx.x;
    int v = (tid < SCAN_BLOCKS) ? g_bsum[tid] : 0;
    sh[tid] = v;
    __syncthreads();
#pragma unroll
    for (int d = 1; d < 128; d <<= 1) {
        int t = (tid >= d) ? sh[tid - d] : 0;
        __syncthreads();
        sh[tid] += t;
        __syncthreads();
    }
    if (tid < SCAN_BLOCKS) g_boff[tid] = sh[tid] - v;
}
__global__ void scan3_kernel() {
    int i = blockIdx.x * SCAN_B + threadIdx.x;
    if (i < NN) {
        int o = g_off[i] + g_boff[blockIdx.x];
        g_off[i] = o;
        g_cur[i] = o;
    }
    if (i == 0) g_off[NN] = NE;
}
// pack (x_idx[src] << 2) | attr  -> direct index into the 76-row message table
__global__ void scatter_kernel(const int* __restrict__ ei, const int* __restrict__ ea,
                               const int* __restrict__ xi) {
    int e = blockIdx.x * blockDim.x + threadIdx.x;
    if (e >= NE) return;
    int src = __ldg(ei + e);
    int dst = __ldg(ei + NE + e);
    int attr = __ldg(ea + e);
    int xis = __ldg(xi + src);
    int p = atomicAdd(&g_cur[dst], 1);
    g_list[p] = (xis << 2) | attr;
}

// ---------------- aggregate layer 0: M[n] = nemb[xi[n]] + sum g_T[pk] ----------------
// All gathered rows are L1-resident (19-row nemb = 9.7KB, 76-row table = 38.9KB).
__global__ void aggregate0_kernel(const int* __restrict__ xi, const float* __restrict__ nemb,
                                  float* __restrict__ M) {
    int node = (blockIdx.x * blockDim.x + threadIdx.x) >> 5;
    int lane = threadIdx.x & 31;
    if (node >= NN) return;
    int s = g_off[node];
    int e = g_off[node + 1];
    float4 acc = __ldg((const float4*)(nemb + (size_t)__ldg(xi + node) * HID) + lane);
    for (int i = s; i < e; i++) {
        int pk = __ldg(g_list + i);
        float4 m = __ldg((const float4*)(g_T + (size_t)pk * HID) + lane);
        acc.x += m.x;
        acc.y += m.y;
        acc.z += m.z;
        acc.w += m.w;
    }
    *((float4*)(M + node * HID) + lane) = acc;
}

// ---------------- aggregate layer >=1: M[n] = norm(R[n]) + sum relu(norm(R[src])+eemb[attr]) ----------------
// Note pk = (xi[src]<<2)|attr no longer carries src id, so layer-1 needs its own list.
// Instead we keep a second list with (src<<2)|attr packed at scatter time.
__device__ int g_list2[NE];
__global__ void scatter2_kernel(const int* __restrict__ ei, const int* __restrict__ ea) {
    int e = blockIdx.x * blockDim.x + threadIdx.x;
    if (e >= NE) return;
    int src = __ldg(ei + e);
    int dst = __ldg(ei + NE + e);
    int attr = __ldg(ea + e);
    int p = atomicAdd(&g_cur[dst], 1);
    g_list2[p] = (src << 2) | attr;
}
__global__ void reset_cur_kernel() {
    int i = blockIdx.x * blockDim.x + threadIdx.x;
    if (i < NN) g_cur[i] = g_off[i];
}
__global__ void aggregate1_kernel(const float* __restrict__ X, float* __restrict__ M,
                                  const float* __restrict__ eemb) {
    int node = (blockIdx.x * blockDim.x + threadIdx.x) >> 5;
    int lane = threadIdx.x & 31;
    if (node >= NN) return;
    float4 sc = *(const float4*)(g_scale + lane * 4);
    float4 sh = *(const float4*)(g_shift + lane * 4);
    int s = g_off[node];
    int e = g_off[node + 1];
    float4 acc = __ldg((const float4*)(X + node * HID) + lane);
    acc.x = fmaf(acc.x, sc.x, sh.x);
    acc.y = fmaf(acc.y, sc.y, sh.y);
    acc.z = fmaf(acc.z, sc.z, sh.z);
    acc.w = fmaf(acc.w, sc.w, sh.w);
    for (int i = s; i < e; i++) {
        int pk = __ldg(g_list2 + i);
        int src = pk >> 2, attr = pk & 3;
        float4 x4 = __ldg((const float4*)(X + (size_t)src * HID) + lane);
        float4 e4 = __ldg((const float4*)(eemb + attr * HID) + lane);
        float a, b, c, d;
        a = fmaf(x4.x, sc.x, sh.x) + e4.x;
        b = fmaf(x4.y, sc.y, sh.y) + e4.y;
        c = fmaf(x4.z, sc.z, sh.z) + e4.z;
        d = fmaf(x4.w, sc.w, sh.w) + e4.w;
        acc.x += fmaxf(a, 0.f);
        acc.y += fmaxf(b, 0.f);
        acc.z += fmaxf(c, 0.f);
        acc.w += fmaxf(d, 0.f);
    }
    *((float4*)(M + node * HID) + lane) = acc;
}

// ---------------- fused 3xTF32 double-GEMM: R = relu(relu(M@W1+b1)@W2+b2) ----------------
#define MTILE 128
#define RS 36
#define RS2 132
#define RAW_WORDS (MTILE * RS)
#define STAT_OFF (2 * RAW_WORDS)
#define AS_OFF (STAT_OFF + 256)
#define SMEM_GEMM ((AS_OFF + MTILE * RS2) * 4)

__global__ void __launch_bounds__(256, 2)
fused_gemm_kernel(const float* __restrict__ M, const uint4* __restrict__ Wf1,
                  const float* __restrict__ b1, const uint4* __restrict__ Wf2,
                  const float* __restrict__ b2, float* __restrict__ R) {
    extern __shared__ char smem[];
    float* raw = (float*)smem;
    float* ssum = (float*)smem + STAT_OFF;
    float* ssq = ssum + 128;
    float* As = (float*)smem + AS_OFF;

    uint32_t rawAddr;
    asm("{ .reg .u64 t; cvta.to.shared.u64 t, %1; cvt.u32.u64 %0, t; }"
        : "=r"(rawAddr) : "l"(smem));

    int tid = threadIdx.x, wid = tid >> 5, lane = tid & 31;
    int wm = wid & 3, wn = wid >> 2;
    int g = lane >> 2, tg = lane & 3;
    int rowBase = blockIdx.x * MTILE;

    ssum[tid] = 0.f;

    auto issue_chunk = [&](int chunk, int buf) {
#pragma unroll
        for (int j = 0; j < 4; j++) {
            int i = tid + j * 256;
            int r = i >> 3, q = i & 7;
            int grow = rowBase + r;
            const float* src = M + (size_t)min(grow, NN - 1) * HID + chunk * 32 + q * 4;
            uint32_t dst = rawAddr + (uint32_t)(buf * RAW_WORDS + r * RS + q * 4) * 4u;
            int sz = (grow < NN) ? 16 : 0;
            asm volatile("cp.async.cg.shared.global [%0], [%1], 16, %2;"
                         :: "r"(dst), "l"(src), "r"(sz));
        }
        asm volatile("cp.async.commit_group;");
    };
    issue_chunk(0, 0);
    issue_chunk(1, 1);

    float acc[2][8][4];
#pragma unroll
    for (int mt = 0; mt < 2; mt++)
#pragma unroll
        for (int nt = 0; nt < 8; nt++)
#pragma unroll
            for (int c = 0; c < 4; c++) acc[mt][nt][c] = 0.f;

    // ---------------- phase 1 mainloop: acc1 = M @ W1 ----------------
    const uint4* wfw1 = Wf1 + (size_t)(wn * 8) * 32 + lane;
#pragma unroll
    for (int chunk = 0; chunk < 4; chunk++) {
        if (chunk < 3) asm volatile("cp.async.wait_group 1;" ::: "memory");
        else           asm volatile("cp.async.wait_group 0;" ::: "memory");
        __syncthreads();
        const float* rb = raw + (chunk & 1) * RAW_WORDS;

#pragma unroll
        for (int ks = 0; ks < 4; ks++) {
            int k0 = ks * 8;
            int kstep = chunk * 4 + ks;
            const uint4* wfk = wfw1 + (size_t)kstep * 16 * 32;

            uint32_t afH[2][4], afL[2][4];
#pragma unroll
            for (int mt = 0; mt < 2; mt++) {
                int r = wm * 32 + mt * 16 + g;
                float v0 = rb[r * RS + k0 + tg];
                float v1 = rb[(r + 8) * RS + k0 + tg];
                float v2 = rb[r * RS + k0 + tg + 4];
                float v3 = rb[(r + 8) * RS + k0 + tg + 4];
                split_tf32(v0, afH[mt][0], afL[mt][0]);
                split_tf32(v1, afH[mt][1], afL[mt][1]);
                split_tf32(v2, afH[mt][2], afL[mt][2]);
                split_tf32(v3, afH[mt][3], afL[mt][3]);
            }
#pragma unroll
            for (int hb = 0; hb < 2; hb++) {
                uint4 bf[4];
#pragma unroll
                for (int q = 0; q < 4; q++)
                    bf[q] = __ldg(wfk + (hb * 4 + q) * 32);
#pragma unroll
                for (int mt = 0; mt < 2; mt++)
#pragma unroll
                    for (int q = 0; q < 4; q++) {
                        int nt = hb * 4 + q;
                        uint32_t bh[2] = {bf[q].x, bf[q].y};
                        uint32_t bl[2] = {bf[q].z, bf[q].w};
                        MMA_TF32(acc[mt][nt], afH[mt], bl);
                        MMA_TF32(acc[mt][nt], afL[mt], bh);
                        MMA_TF32(acc[mt][nt], afH[mt], bh);
                    }
            }
        }
        __syncthreads();
        if (chunk < 2) issue_chunk(chunk + 2, chunk & 1);
    }

    // ---------------- phase 1 epilogue: As = relu(acc1 + b1) ----------------
#pragma unroll
    for (int nt = 0; nt < 8; nt++) {
        int col = wn * 64 + nt * 8 + tg * 2;
        float2 bv = __ldg((const float2*)(b1 + col));
#pragma unroll
        for (int mt = 0; mt < 2; mt++) {
            int r = wm * 32 + mt * 16 + g;
            float2 oa, ob;
            oa.x = fmaxf(acc[mt][nt][0] + bv.x, 0.f);
            oa.y = fmaxf(acc[mt][nt][1] + bv.y, 0.f);
            ob.x = fmaxf(acc[mt][nt][2] + bv.x, 0.f);
            ob.y = fmaxf(acc[mt][nt][3] + bv.y, 0.f);
            *(float2*)(As + r * RS2 + col) = oa;
            *(float2*)(As + (r + 8) * RS2 + col) = ob;
            acc[mt][nt][0] = 0.f; acc[mt][nt][1] = 0.f;
            acc[mt][nt][2] = 0.f; acc[mt][nt][3] = 0.f;
        }
    }
    __syncthreads();

    // ---------------- phase 2 mainloop: acc2 = As @ W2 ----------------
    const uint4* wfw2 = Wf2 + (size_t)(wn * 8) * 32 + lane;
#pragma unroll
    for (int kstep = 0; kstep < 16; kstep++) {
        int k0 = kstep * 8;
        const uint4* wfk = wfw2 + (size_t)kstep * 16 * 32;

        uint32_t afH[2][4], afL[2][4];
#pragma unroll
        for (int mt = 0; mt < 2; mt++) {
            int r = wm * 32 + mt * 16 + g;
            float v0 = As[r * RS2 + k0 + tg];
            float v1 = As[(r + 8) * RS2 + k0 + tg];
            float v2 = As[r * RS2 + k0 + tg + 4];
            float v3 = As[(r + 8) * RS2 + k0 + tg + 4];
            split_tf32(v0, afH[mt][0], afL[mt][0]);
            split_tf32(v1, afH[mt][1], afL[mt][1]);
            split_tf32(v2, afH[mt][2], afL[mt][2]);
            split_tf32(v3, afH[mt][3], afL[mt][3]);
        }
#pragma unroll
        for (int hb = 0; hb < 2; hb++) {
            uint4 bf[4];
#pragma unroll
            for (int q = 0; q < 4; q++)
                bf[q] = __ldg(wfk + (hb * 4 + q) * 32);
#pragma unroll
            for (int mt = 0; mt < 2; mt++)
#pragma unroll
                for (int q = 0; q < 4; q++) {
                    int nt = hb * 4 + q;
                    uint32_t bh[2] = {bf[q].x, bf[q].y};
                    uint32_t bl[2] = {bf[q].z, bf[q].w};
                    MMA_TF32(acc[mt][nt], afH[mt], bl);
                    MMA_TF32(acc[mt][nt], afL[mt], bh);
                    MMA_TF32(acc[mt][nt], afH[mt], bh);
                }
        }
    }

    // ---------------- phase 2 epilogue: R = relu(acc2 + b2), column stats ----------------
#pragma unroll
    for (int nt = 0; nt < 8; nt++) {
        int col = wn * 64 + nt * 8 + tg * 2;
        float2 bv = __ldg((const float2*)(b2 + col));
        float s0 = 0.f, s1 = 0.f, q0 = 0.f, q1 = 0.f;
#pragma unroll
        for (int mt = 0; mt < 2; mt++) {
            int r0 = rowBase + wm * 32 + mt * 16 + g;
            float2 oa, ob;
            oa.x = fmaxf(acc[mt][nt][0] + bv.x, 0.f);
            oa.y = fmaxf(acc[mt][nt][1] + bv.y, 0.f);
            ob.x = fmaxf(acc[mt][nt][2] + bv.x, 0.f);
            ob.y = fmaxf(acc[mt][nt][3] + bv.y, 0.f);
            if (r0 < NN) {
                *(float2*)(R + r0 * HID + col) = oa;
                s0 += oa.x; q0 += oa.x * oa.x; s1 += oa.y; q1 += oa.y * oa.y;
            }
            if (r0 + 8 < NN) {
                *(float2*)(R + (r0 + 8) * HID + col) = ob;
                s0 += ob.x; q0 += ob.x * ob.x; s1 += ob.y; q1 += ob.y * ob.y;
            }
        }
#pragma unroll
        for (int m = 16; m >= 4; m >>= 1) {
            s0 += __shfl_xor_sync(0xffffffff, s0, m);
            s1 += __shfl_xor_sync(0xffffffff, s1, m);
            q0 += __shfl_xor_sync(0xffffffff, q0, m);
            q1 += __shfl_xor_sync(0xffffffff, q1, m);
        }
        if (lane < 4) {
            int c0 = wn * 64 + nt * 8 + lane * 2;
            atomicAdd(&ssum[c0], s0);
            atomicAdd(&ssum[c0 + 1], s1);
            atomicAdd(&ssq[c0], q0);
            atomicAdd(&ssq[c0 + 1], q1);
        }
    }
    __syncthreads();
    if (tid < 128) {
        atomicAdd(&g_sum[tid], (double)ssum[tid]);
        atomicAdd(&g_sumsq[tid], (double)ssq[tid]);
    }
}

// ---------------- finalize: scale/shift from stats; reset accumulators; optional out-zero ----------------
__global__ void finalize_kernel(const float* __restrict__ gw, const float* __restrict__ bw,
                                float* __restrict__ outz) {
    int c = threadIdx.x;
    double mu = g_sum[c] / (double)NN;
    double var = g_sumsq[c] / (double)NN - mu * mu;
    float sc = (float)((double)gw[c] * rsqrt(var + 1e-5));
    g_scale[c] = sc;
    g_shift[c] = bw[c] - (float)mu * sc;
    g_sum[c] = 0.0;
    g_sumsq[c] = 0.0;
    if (outz) {
        float4 z = make_float4(0.f, 0.f, 0.f, 0.f);
#pragma unroll
        for (int j = 0; j < NG * HID / 4 / 128; j++)
            ((float4*)outz)[c + j * 128] = z;
    }
}

// ---------------- pooling (applies final norm inline) ----------------
__global__ void pool_kernel(const float* __restrict__ R, const int* __restrict__ batch,
                            float* __restrict__ out) {
    int warp = (blockIdx.x * blockDim.x + threadIdx.x) >> 5;
    int lane = threadIdx.x & 31;
    if (warp >= NN) return;
    float4 sc = *(const float4*)(g_scale + lane * 4);
    float4 sh = *(const float4*)(g_shift + lane * 4);
    int g = __ldg(batch + warp);
    float4 v = __ldg((const float4*)(R + warp * HID) + lane);
    v.x = fmaf(v.x, sc.x, sh.x);
    v.y = fmaf(v.y, sc.y, sh.y);
    v.z = fmaf(v.z, sc.z, sh.z);
    v.w = fmaf(v.w, sc.w, sh.w);
    float* p = out + g * HID + lane * 4;
    asm volatile("red.global.add.v4.f32 [%0], {%1,%2,%3,%4};"
                 :: "l"(p), "f"(v.x), "f"(v.y), "f"(v.z), "f"(v.w) : "memory");
}

// ---------------- host ----------------
extern "C" void kernel_launch(void* const* d_in, const int* in_sizes, int n_in,
                              void* d_out, int out_size) {
    const int*   x_idx      = (const int*)d_in[0];
    const int*   edge_index = (const int*)d_in[1];
    const int*   edge_attr  = (const int*)d_in[2];
    const int*   batch      = (const int*)d_in[3];
    const float* node_emb   = (const float*)d_in[4];
    const float* edge_emb   = (const float*)d_in[5];
    const float* W1         = (const float*)d_in[6];
    const float* b1         = (const float*)d_in[7];
    const float* W2         = (const float*)d_in[8];
    const float* b2         = (const float*)d_in[9];
    const float* bn_g       = (const float*)d_in[10];
    const float* bn_b       = (const float*)d_in[11];
    float* out = (float*)d_out;

    cudaFuncSetAttribute(fused_gemm_kernel,
                         cudaFuncAttributeMaxDynamicSharedMemorySize, SMEM_GEMM);

    float *M, *R;
    uint4* Wf;
    cudaGetSymbolAddress((void**)&M, g_M);
    cudaGetSymbolAddress((void**)&R, g_R);
    cudaGetSymbolAddress((void**)&Wf, g_Wf);

    int gemmBlocks = (NN + MTILE - 1) / MTILE;

    prep_w_kernel<<<(4 * HID * HID + 255) / 256, 256>>>(W1, W2, node_emb, edge_emb);
    hist_kernel<<<(NE + 255) / 256, 256>>>(edge_index);
    scan1_kernel<<<SCAN_BLOCKS, SCAN_B>>>();
    scan2_kernel<<<1, 128>>>();
    scan3_kernel<<<SCAN_BLOCKS, SCAN_B>>>();
    scatter_kernel<<<(NE + 255) / 256, 256>>>(edge_index, edge_attr, x_idx);
    reset_cur_kernel<<<(NN + 255) / 256, 256>>>();
    scatter2_kernel<<<(NE + 255) / 256, 256>>>(edge_index, edge_attr);

    for (int l = 0; l < NL; l++) {
        if (l == 0)
            aggregate0_kernel<<<(NN * 32 + 255) / 256, 256>>>(x_idx, node_emb, M);
        else
            aggregate1_kernel<<<(NN * 32 + 255) / 256, 256>>>(R, M, edge_emb);
        fused_gemm_kernel<<<gemmBlocks, 256, SMEM_GEMM>>>(
            M, Wf + (size_t)(l * 2 + 0) * 8192, b1 + l * HID,
            Wf + (size_t)(l * 2 + 1) * 8192, b2 + l * HID, R);
        finalize_kernel<<<1, 128>>>(bn_g + l * HID, bn_b + l * HID,
                                    (l == NL - 1) ? out : nullptr);
    }

    pool_kernel<<<NN * 32 / 256, 256>>>(R, batch, out);
}